// round 10
// baseline (speedup 1.0000x reference)
#include <cuda_runtime.h>
#include <cuda_fp16.h>
#include <math.h>

#define BB 8
#define NN 8192
#define SS 8
#define MROWS (BB * NN)          // 65536 tokens
#define DIN 64
#define DH  128                  // hidden
#define DOUT 64

// Scratch: A part fp32 (32 MB), B|C parts fp16 (32 MB), G fp32 (32 MB)
__device__ float  g_A [(size_t)MROWS * DH];
__device__ __half g_BC[(size_t)MROWS * 2 * DH];
__device__ float  g_G [(size_t)MROWS * DH];

typedef unsigned long long u64;

// --- packed f32x2 helpers ---
__device__ __forceinline__ u64 pack2(float x) {
    u64 r; unsigned int u = __float_as_uint(x);
    asm("mov.b64 %0, {%1, %1};" : "=l"(r) : "r"(u));
    return r;
}
__device__ __forceinline__ void ffma2(u64& d, u64 a, u64 b) {
    asm("fma.rn.f32x2 %0, %1, %2, %0;" : "+l"(d) : "l"(a), "l"(b));
}
__device__ __forceinline__ void addf2(u64& d, u64 b) {
    asm("add.rn.f32x2 %0, %0, %1;" : "+l"(d) : "l"(b));
}

// tanh-form GELU with HW MUFU.TANH.
__device__ __forceinline__ float gelu_fast(float x) {
    float x2 = x * x;
    float u  = x * (0.7978845608028654f + 0.035677408136300125f * x2);
    float t;
    asm("tanh.approx.f32 %0, %1;" : "=f"(t) : "f"(u));
    return 0.5f * x * (1.0f + t);
}

// ---------------------------------------------------------------------------
// Kernel 1: [A|B|C] = X (65536 x 64) @ W1-as-(64 x 384)   [+ b1 on part 0]
//   part 0 -> g_A fp32; parts 1,2 -> g_BC fp16.
//   No reg-prefetch; 3 CTAs/SM for latency hiding (launch_bounds caps regs).
// ---------------------------------------------------------------------------
__global__ __launch_bounds__(256, 3) void k1_gemm(const float* __restrict__ X,
                                                  const float* __restrict__ W1,
                                                  const float* __restrict__ b1)
{
    __shared__ float XsT[32][132];   // [k][row] transposed, padded
    __shared__ float Ws [32][128];   // [k][col_local]

    const int tid  = threadIdx.x;
    const int m0   = blockIdx.x * 128;
    const int part = blockIdx.y;           // 0..2

    const int tx = tid & 15;
    const int ty = tid >> 4;
    // acc[i][p]: row ty*8+i; p=0,1 -> cols tx*4+{01,23}; p=2,3 -> cols 64+tx*4+{01,23}
    u64 acc[8][4];
    #pragma unroll
    for (int i = 0; i < 8; i++)
        #pragma unroll
        for (int p = 0; p < 4; p++) acc[i][p] = 0ULL;

    #pragma unroll
    for (int kb = 0; kb < 2; kb++) {
        // X slice: 128 rows x 32 k, transpose into XsT
        #pragma unroll
        for (int i = 0; i < 4; i++) {
            int lin = tid + i * 256;
            int row = lin >> 3;
            int kq  = lin & 7;
            float4 v = *(const float4*)&X[(size_t)(m0 + row) * DIN + kb * 32 + kq * 4];
            XsT[kq * 4 + 0][row] = v.x;
            XsT[kq * 4 + 1][row] = v.y;
            XsT[kq * 4 + 2][row] = v.z;
            XsT[kq * 4 + 3][row] = v.w;
        }
        // W slice
        #pragma unroll
        for (int i = 0; i < 4; i++) {
            int lin = tid + i * 256;
            int k   = lin >> 5;
            int cq  = lin & 31;
            *(float4*)&Ws[k][cq * 4] =
                *(const float4*)&W1[(size_t)(part * 64 + kb * 32 + k) * DH + cq * 4];
        }
        __syncthreads();

        #pragma unroll
        for (int k = 0; k < 32; k++) {
            float xv[8];
            *(float4*)&xv[0] = *(const float4*)&XsT[k][ty * 8];
            *(float4*)&xv[4] = *(const float4*)&XsT[k][ty * 8 + 4];
            ulonglong2 w01 = *(const ulonglong2*)&Ws[k][tx * 4];
            ulonglong2 w23 = *(const ulonglong2*)&Ws[k][64 + tx * 4];
            #pragma unroll
            for (int i = 0; i < 8; i++) {
                u64 xp = pack2(xv[i]);
                ffma2(acc[i][0], xp, w01.x);
                ffma2(acc[i][1], xp, w01.y);
                ffma2(acc[i][2], xp, w23.x);
                ffma2(acc[i][3], xp, w23.y);
            }
        }
        __syncthreads();
    }

    if (part == 0) {
        ulonglong2 bb0 = *(const ulonglong2*)&b1[tx * 4];
        ulonglong2 bb1 = *(const ulonglong2*)&b1[64 + tx * 4];
        #pragma unroll
        for (int i = 0; i < 8; i++) {
            addf2(acc[i][0], bb0.x); addf2(acc[i][1], bb0.y);
            addf2(acc[i][2], bb1.x); addf2(acc[i][3], bb1.y);
            float* dst = &g_A[(size_t)(m0 + ty * 8 + i) * DH];
            *(ulonglong2*)&dst[tx * 4]      = make_ulonglong2(acc[i][0], acc[i][1]);
            *(ulonglong2*)&dst[64 + tx * 4] = make_ulonglong2(acc[i][2], acc[i][3]);
        }
    } else {
        const int poff = (part - 1) * DH;
        #pragma unroll
        for (int i = 0; i < 8; i++) {
            __half* dst = &g_BC[(size_t)(m0 + ty * 8 + i) * (2 * DH) + poff];
            __half2 h0 = __float22half2_rn(*(float2*)&acc[i][0]);
            __half2 h1 = __float22half2_rn(*(float2*)&acc[i][1]);
            __half2 h2 = __float22half2_rn(*(float2*)&acc[i][2]);
            __half2 h3 = __float22half2_rn(*(float2*)&acc[i][3]);
            *(__half2*)&dst[tx * 4]          = h0;
            *(__half2*)&dst[tx * 4 + 2]      = h1;
            *(__half2*)&dst[64 + tx * 4]     = h2;
            *(__half2*)&dst[64 + tx * 4 + 2] = h3;
        }
    }
}

// ---------------------------------------------------------------------------
// Kernel 2: gather + GELU + mean. One warp per token. fp16 B/C gathers.
// ---------------------------------------------------------------------------
__global__ __launch_bounds__(256, 6) void k2_gather(const int* __restrict__ j_idx,
                                                    const int* __restrict__ k_idx)
{
    const int tid  = threadIdx.x;
    const int warp = tid >> 5;
    const int lane = tid & 31;
    const int m    = blockIdx.x * 8 + warp;
    const int base = m & ~(NN - 1);        // b * N

    float4 a = *(const float4*)&g_A[(size_t)m * DH + lane * 4];

    int4 j03 = *(const int4*)&j_idx[(size_t)m * SS];
    int4 j47 = *(const int4*)&j_idx[(size_t)m * SS + 4];
    int4 k03 = *(const int4*)&k_idx[(size_t)m * SS];
    int4 k47 = *(const int4*)&k_idx[(size_t)m * SS + 4];
    int js[8] = { j03.x, j03.y, j03.z, j03.w, j47.x, j47.y, j47.z, j47.w };
    int ks[8] = { k03.x, k03.y, k03.z, k03.w, k47.x, k47.y, k47.z, k47.w };

    float4 acc = make_float4(0.f, 0.f, 0.f, 0.f);
    #pragma unroll
    for (int s = 0; s < SS; s++) {
        // 8-byte gathers: 4 halfs each from B part and C part
        const __half2* bp = (const __half2*)&g_BC[(size_t)(base + js[s]) * (2*DH) + lane * 4];
        const __half2* cp = (const __half2*)&g_BC[(size_t)(base + ks[s]) * (2*DH) + DH + lane * 4];
        uint2 bu = *(const uint2*)bp;
        uint2 cu = *(const uint2*)cp;
        float2 b01 = __half22float2(*(const __half2*)&bu.x);
        float2 b23 = __half22float2(*(const __half2*)&bu.y);
        float2 c01 = __half22float2(*(const __half2*)&cu.x);
        float2 c23 = __half22float2(*(const __half2*)&cu.y);
        acc.x += gelu_fast(a.x + b01.x + c01.x);
        acc.y += gelu_fast(a.y + b01.y + c01.y);
        acc.z += gelu_fast(a.z + b23.x + c23.x);
        acc.w += gelu_fast(a.w + b23.y + c23.y);
    }
    acc.x *= 0.125f; acc.y *= 0.125f; acc.z *= 0.125f; acc.w *= 0.125f;

    *(float4*)&g_G[(size_t)m * DH + lane * 4] = acc;   // coalesced
}

// ---------------------------------------------------------------------------
// Kernel 3: OUT (65536 x 64) = G (65536 x 128) @ W2 (128 x 64) + b2  (f32x2)
// ---------------------------------------------------------------------------
__global__ __launch_bounds__(256, 2) void k3_gemm(const float* __restrict__ W2,
                                                  const float* __restrict__ b2,
                                                  float* __restrict__ out)
{
    __shared__ float GsT[32][132];   // [k][row] transposed, padded
    __shared__ float W2s[32][64];    // [k][o]

    const int tid = threadIdx.x;
    const int m0  = blockIdx.x * 128;
    const int tx  = tid & 15;
    const int ty  = tid >> 4;

    u64 acc[8][2];
    #pragma unroll
    for (int i = 0; i < 8; i++) { acc[i][0] = 0ULL; acc[i][1] = 0ULL; }

    for (int ksg = 0; ksg < 4; ksg++) {
        #pragma unroll
        for (int i = 0; i < 4; i++) {
            int lin = tid + i * 256;
            int row = lin >> 3;
            int kq  = lin & 7;
            float4 v = *(const float4*)&g_G[(size_t)(m0 + row) * DH + ksg * 32 + kq * 4];
            GsT[kq * 4 + 0][row] = v.x;
            GsT[kq * 4 + 1][row] = v.y;
            GsT[kq * 4 + 2][row] = v.z;
            GsT[kq * 4 + 3][row] = v.w;
        }
        #pragma unroll
        for (int i = 0; i < 2; i++) {
            int lin = tid + i * 256;
            int k   = lin >> 4;
            int cq  = lin & 15;
            *(float4*)&W2s[k][cq * 4] =
                *(const float4*)&W2[(size_t)(ksg * 32 + k) * DOUT + cq * 4];
        }
        __syncthreads();

        #pragma unroll
        for (int k = 0; k < 32; k++) {
            float gv[8];
            *(float4*)&gv[0] = *(const float4*)&GsT[k][ty * 8];
            *(float4*)&gv[4] = *(const float4*)&GsT[k][ty * 8 + 4];
            ulonglong2 w = *(const ulonglong2*)&W2s[k][tx * 4];
            #pragma unroll
            for (int i = 0; i < 8; i++) {
                u64 gp = pack2(gv[i]);
                ffma2(acc[i][0], gp, w.x);
                ffma2(acc[i][1], gp, w.y);
            }
        }
        __syncthreads();
    }

    ulonglong2 bb = *(const ulonglong2*)&b2[tx * 4];
    #pragma unroll
    for (int i = 0; i < 8; i++) {
        addf2(acc[i][0], bb.x);
        addf2(acc[i][1], bb.y);
        *(ulonglong2*)&out[(size_t)(m0 + ty * 8 + i) * DOUT + tx * 4] =
            make_ulonglong2(acc[i][0], acc[i][1]);
    }
}

// ---------------------------------------------------------------------------
extern "C" void kernel_launch(void* const* d_in, const int* in_sizes, int n_in,
                              void* d_out, int out_size)
{
    const float* x     = (const float*)d_in[0];
    const int*   j_idx = (const int*)  d_in[1];
    const int*   k_idx = (const int*)  d_in[2];
    const float* W1    = (const float*)d_in[3];
    const float* b1    = (const float*)d_in[4];
    const float* W2    = (const float*)d_in[5];
    const float* b2    = (const float*)d_in[6];
    float*       out   = (float*)d_out;

    dim3 g1(MROWS / 128, 3);
    k1_gemm<<<g1, 256>>>(x, W1, b1);
    k2_gather<<<MROWS / 8, 256>>>(j_idx, k_idx);
    k3_gemm<<<MROWS / 128, 256>>>(W2, b2, out);
}

// round 11
// speedup vs baseline: 2.2319x; 2.2319x over previous
#include <cuda_runtime.h>
#include <cuda_fp16.h>
#include <math.h>

#define BB 8
#define NN 8192
#define SS 8
#define MROWS (BB * NN)          // 65536 tokens
#define DIN 64
#define DH  128                  // hidden
#define DOUT 64

// Scratch: A part fp32 (32 MB), B|C parts fp16 (32 MB), G fp32 (32 MB)
__device__ float  g_A [(size_t)MROWS * DH];
__device__ __half g_BC[(size_t)MROWS * 2 * DH];
__device__ float  g_G [(size_t)MROWS * DH];

typedef unsigned long long u64;

// --- packed f32x2 helpers ---
__device__ __forceinline__ u64 pack2(float x) {
    u64 r; unsigned int u = __float_as_uint(x);
    asm("mov.b64 %0, {%1, %1};" : "=l"(r) : "r"(u));
    return r;
}
__device__ __forceinline__ void ffma2(u64& d, u64 a, u64 b) {
    asm("fma.rn.f32x2 %0, %1, %2, %0;" : "+l"(d) : "l"(a), "l"(b));
}
__device__ __forceinline__ void addf2(u64& d, u64 b) {
    asm("add.rn.f32x2 %0, %0, %1;" : "+l"(d) : "l"(b));
}

// tanh-form GELU with HW MUFU.TANH.
__device__ __forceinline__ float gelu_fast(float x) {
    float x2 = x * x;
    float u  = x * (0.7978845608028654f + 0.035677408136300125f * x2);
    float t;
    asm("tanh.approx.f32 %0, %1;" : "=f"(t) : "f"(u));
    return 0.5f * x * (1.0f + t);
}

// ---------------------------------------------------------------------------
// Kernel 1: [A|B|C] = X (65536 x 64) @ W1-as-(64 x 384)   [+ b1 on part 0]
//   R9 structure: 128 regs, 2 CTAs/SM, reg-prefetch of stage-1 tiles,
//   FFMA2 mainloop. Epilogue: part 0 -> g_A fp32, parts 1,2 -> g_BC fp16.
// ---------------------------------------------------------------------------
__global__ __launch_bounds__(256, 2) void k1_gemm(const float* __restrict__ X,
                                                  const float* __restrict__ W1,
                                                  const float* __restrict__ b1)
{
    __shared__ float XsT[32][132];   // [k][row] transposed, padded
    __shared__ float Ws [32][128];   // [k][col_local]

    const int tid  = threadIdx.x;
    const int m0   = blockIdx.x * 128;
    const int part = blockIdx.y;           // 0..2

    int xrow[4], xkq[4];
    #pragma unroll
    for (int i = 0; i < 4; i++) {
        int lin = tid + i * 256;
        xrow[i] = lin >> 3;
        xkq[i]  = lin & 7;
        float4 v = *(const float4*)&X[(size_t)(m0 + xrow[i]) * DIN + xkq[i] * 4];
        XsT[xkq[i] * 4 + 0][xrow[i]] = v.x;
        XsT[xkq[i] * 4 + 1][xrow[i]] = v.y;
        XsT[xkq[i] * 4 + 2][xrow[i]] = v.z;
        XsT[xkq[i] * 4 + 3][xrow[i]] = v.w;
    }
    int wk[4], wcq[4];
    #pragma unroll
    for (int i = 0; i < 4; i++) {
        int lin = tid + i * 256;
        wk[i]  = lin >> 5;
        wcq[i] = lin & 31;
        *(float4*)&Ws[wk[i]][wcq[i] * 4] =
            *(const float4*)&W1[(size_t)(part * 64 + wk[i]) * DH + wcq[i] * 4];
    }

    // prefetch stage 1 (kb=1) into registers
    float4 xr[4], wr[4];
    #pragma unroll
    for (int i = 0; i < 4; i++)
        xr[i] = *(const float4*)&X[(size_t)(m0 + xrow[i]) * DIN + 32 + xkq[i] * 4];
    #pragma unroll
    for (int i = 0; i < 4; i++)
        wr[i] = *(const float4*)&W1[(size_t)(part * 64 + 32 + wk[i]) * DH + wcq[i] * 4];

    __syncthreads();

    const int tx = tid & 15;
    const int ty = tid >> 4;
    // acc[i][p]: row ty*8+i; p=0,1 -> cols tx*4+{01,23}; p=2,3 -> cols 64+tx*4+{01,23}
    u64 acc[8][4];
    #pragma unroll
    for (int i = 0; i < 8; i++)
        #pragma unroll
        for (int p = 0; p < 4; p++) acc[i][p] = 0ULL;

    #pragma unroll
    for (int k = 0; k < 32; k++) {
        float xv[8];
        *(float4*)&xv[0] = *(const float4*)&XsT[k][ty * 8];
        *(float4*)&xv[4] = *(const float4*)&XsT[k][ty * 8 + 4];
        ulonglong2 w01 = *(const ulonglong2*)&Ws[k][tx * 4];        // conflict-free
        ulonglong2 w23 = *(const ulonglong2*)&Ws[k][64 + tx * 4];   // conflict-free
        #pragma unroll
        for (int i = 0; i < 8; i++) {
            u64 xp = pack2(xv[i]);
            ffma2(acc[i][0], xp, w01.x);
            ffma2(acc[i][1], xp, w01.y);
            ffma2(acc[i][2], xp, w23.x);
            ffma2(acc[i][3], xp, w23.y);
        }
    }
    __syncthreads();

    #pragma unroll
    for (int i = 0; i < 4; i++) {
        XsT[xkq[i] * 4 + 0][xrow[i]] = xr[i].x;
        XsT[xkq[i] * 4 + 1][xrow[i]] = xr[i].y;
        XsT[xkq[i] * 4 + 2][xrow[i]] = xr[i].z;
        XsT[xkq[i] * 4 + 3][xrow[i]] = xr[i].w;
        *(float4*)&Ws[wk[i]][wcq[i] * 4] = wr[i];
    }
    __syncthreads();

    #pragma unroll
    for (int k = 0; k < 32; k++) {
        float xv[8];
        *(float4*)&xv[0] = *(const float4*)&XsT[k][ty * 8];
        *(float4*)&xv[4] = *(const float4*)&XsT[k][ty * 8 + 4];
        ulonglong2 w01 = *(const ulonglong2*)&Ws[k][tx * 4];
        ulonglong2 w23 = *(const ulonglong2*)&Ws[k][64 + tx * 4];
        #pragma unroll
        for (int i = 0; i < 8; i++) {
            u64 xp = pack2(xv[i]);
            ffma2(acc[i][0], xp, w01.x);
            ffma2(acc[i][1], xp, w01.y);
            ffma2(acc[i][2], xp, w23.x);
            ffma2(acc[i][3], xp, w23.y);
        }
    }

    if (part == 0) {
        ulonglong2 bb0 = *(const ulonglong2*)&b1[tx * 4];
        ulonglong2 bb1 = *(const ulonglong2*)&b1[64 + tx * 4];
        #pragma unroll
        for (int i = 0; i < 8; i++) {
            addf2(acc[i][0], bb0.x); addf2(acc[i][1], bb0.y);
            addf2(acc[i][2], bb1.x); addf2(acc[i][3], bb1.y);
            float* dst = &g_A[(size_t)(m0 + ty * 8 + i) * DH];
            *(ulonglong2*)&dst[tx * 4]      = make_ulonglong2(acc[i][0], acc[i][1]);
            *(ulonglong2*)&dst[64 + tx * 4] = make_ulonglong2(acc[i][2], acc[i][3]);
        }
    } else {
        const int poff = (part - 1) * DH;
        #pragma unroll
        for (int i = 0; i < 8; i++) {
            __half* dst = &g_BC[(size_t)(m0 + ty * 8 + i) * (2 * DH) + poff];
            __half2 h0 = __float22half2_rn(*(float2*)&acc[i][0]);
            __half2 h1 = __float22half2_rn(*(float2*)&acc[i][1]);
            __half2 h2 = __float22half2_rn(*(float2*)&acc[i][2]);
            __half2 h3 = __float22half2_rn(*(float2*)&acc[i][3]);
            *(__half2*)&dst[tx * 4]          = h0;
            *(__half2*)&dst[tx * 4 + 2]      = h1;
            *(__half2*)&dst[64 + tx * 4]     = h2;
            *(__half2*)&dst[64 + tx * 4 + 2] = h3;
        }
    }
}

// ---------------------------------------------------------------------------
// Kernel 2: gather + GELU + mean. One warp per token. fp16 B/C gathers.
// ---------------------------------------------------------------------------
__global__ __launch_bounds__(256, 6) void k2_gather(const int* __restrict__ j_idx,
                                                    const int* __restrict__ k_idx)
{
    const int tid  = threadIdx.x;
    const int warp = tid >> 5;
    const int lane = tid & 31;
    const int m    = blockIdx.x * 8 + warp;
    const int base = m & ~(NN - 1);        // b * N

    float4 a = *(const float4*)&g_A[(size_t)m * DH + lane * 4];

    int4 j03 = *(const int4*)&j_idx[(size_t)m * SS];
    int4 j47 = *(const int4*)&j_idx[(size_t)m * SS + 4];
    int4 k03 = *(const int4*)&k_idx[(size_t)m * SS];
    int4 k47 = *(const int4*)&k_idx[(size_t)m * SS + 4];
    int js[8] = { j03.x, j03.y, j03.z, j03.w, j47.x, j47.y, j47.z, j47.w };
    int ks[8] = { k03.x, k03.y, k03.z, k03.w, k47.x, k47.y, k47.z, k47.w };

    float4 acc = make_float4(0.f, 0.f, 0.f, 0.f);
    #pragma unroll
    for (int s = 0; s < SS; s++) {
        const uint2 bu = *(const uint2*)&g_BC[(size_t)(base + js[s]) * (2*DH) + lane * 4];
        const uint2 cu = *(const uint2*)&g_BC[(size_t)(base + ks[s]) * (2*DH) + DH + lane * 4];
        float2 b01 = __half22float2(*(const __half2*)&bu.x);
        float2 b23 = __half22float2(*(const __half2*)&bu.y);
        float2 c01 = __half22float2(*(const __half2*)&cu.x);
        float2 c23 = __half22float2(*(const __half2*)&cu.y);
        acc.x += gelu_fast(a.x + b01.x + c01.x);
        acc.y += gelu_fast(a.y + b01.y + c01.y);
        acc.z += gelu_fast(a.z + b23.x + c23.x);
        acc.w += gelu_fast(a.w + b23.y + c23.y);
    }
    acc.x *= 0.125f; acc.y *= 0.125f; acc.z *= 0.125f; acc.w *= 0.125f;

    *(float4*)&g_G[(size_t)m * DH + lane * 4] = acc;   // coalesced
}

// ---------------------------------------------------------------------------
// Kernel 3: OUT (65536 x 64) = G (65536 x 128) @ W2 (128 x 64) + b2  (f32x2)
// ---------------------------------------------------------------------------
__global__ __launch_bounds__(256, 2) void k3_gemm(const float* __restrict__ W2,
                                                  const float* __restrict__ b2,
                                                  float* __restrict__ out)
{
    __shared__ float GsT[32][132];   // [k][row] transposed, padded
    __shared__ float W2s[32][64];    // [k][o]

    const int tid = threadIdx.x;
    const int m0  = blockIdx.x * 128;
    const int tx  = tid & 15;
    const int ty  = tid >> 4;

    u64 acc[8][2];
    #pragma unroll
    for (int i = 0; i < 8; i++) { acc[i][0] = 0ULL; acc[i][1] = 0ULL; }

    for (int ksg = 0; ksg < 4; ksg++) {
        #pragma unroll
        for (int i = 0; i < 4; i++) {
            int lin = tid + i * 256;
            int row = lin >> 3;
            int kq  = lin & 7;
            float4 v = *(const float4*)&g_G[(size_t)(m0 + row) * DH + ksg * 32 + kq * 4];
            GsT[kq * 4 + 0][row] = v.x;
            GsT[kq * 4 + 1][row] = v.y;
            GsT[kq * 4 + 2][row] = v.z;
            GsT[kq * 4 + 3][row] = v.w;
        }
        #pragma unroll
        for (int i = 0; i < 2; i++) {
            int lin = tid + i * 256;
            int k   = lin >> 4;
            int cq  = lin & 15;
            *(float4*)&W2s[k][cq * 4] =
                *(const float4*)&W2[(size_t)(ksg * 32 + k) * DOUT + cq * 4];
        }
        __syncthreads();

        #pragma unroll
        for (int k = 0; k < 32; k++) {
            float gv[8];
            *(float4*)&gv[0] = *(const float4*)&GsT[k][ty * 8];
            *(float4*)&gv[4] = *(const float4*)&GsT[k][ty * 8 + 4];
            ulonglong2 w = *(const ulonglong2*)&W2s[k][tx * 4];
            #pragma unroll
            for (int i = 0; i < 8; i++) {
                u64 gp = pack2(gv[i]);
                ffma2(acc[i][0], gp, w.x);
                ffma2(acc[i][1], gp, w.y);
            }
        }
        __syncthreads();
    }

    ulonglong2 bb = *(const ulonglong2*)&b2[tx * 4];
    #pragma unroll
    for (int i = 0; i < 8; i++) {
        addf2(acc[i][0], bb.x);
        addf2(acc[i][1], bb.y);
        *(ulonglong2*)&out[(size_t)(m0 + ty * 8 + i) * DOUT + tx * 4] =
            make_ulonglong2(acc[i][0], acc[i][1]);
    }
}

// ---------------------------------------------------------------------------
extern "C" void kernel_launch(void* const* d_in, const int* in_sizes, int n_in,
                              void* d_out, int out_size)
{
    const float* x     = (const float*)d_in[0];
    const int*   j_idx = (const int*)  d_in[1];
    const int*   k_idx = (const int*)  d_in[2];
    const float* W1    = (const float*)d_in[3];
    const float* b1    = (const float*)d_in[4];
    const float* W2    = (const float*)d_in[5];
    const float* b2    = (const float*)d_in[6];
    float*       out   = (float*)d_out;

    dim3 g1(MROWS / 128, 3);
    k1_gemm<<<g1, 256>>>(x, W1, b1);
    k2_gather<<<MROWS / 8, 256>>>(j_idx, k_idx);
    k3_gemm<<<MROWS / 128, 256>>>(W2, b2, out);
}